// round 14
// baseline (speedup 1.0000x reference)
#include <cuda_runtime.h>
#include <cuda_fp16.h>
#include <math.h>
#include <stdint.h>

// R14: single-stream chain (R11 structure, half-split reverted as neutral);
// fp32->fp16 activation convert fused into QKV A-producer (convert kernel
// deleted); attention as one 256-CTA launch, heavy causal tiles first.

// ---------------------------------------------------------------------------
// Problem constants
// ---------------------------------------------------------------------------
#define SEQ_N 2048
#define SEQ_M 2048
#define TOTK  (SEQ_N + SEQ_M)   // 4096
#define DIM   1024
#define HEADS 16
#define DH    64
#define DFF_  4096
#define MASK_VAL (-50000.0f)

// ---------------------------------------------------------------------------
// Scratch (device globals; no allocation allowed)
// ---------------------------------------------------------------------------
__device__ __half g_qh  [SEQ_N * DIM];
__device__ __half g_kvh [TOTK * 2 * DIM];
__device__ __half g_attnh[SEQ_N * DIM];
__device__ __half g_x1h [SEQ_N * DIM];
__device__ __half g_ffh [SEQ_N * DFF_];
__device__ float  g_t   [SEQ_N * DIM];
__device__ float  g_x1  [SEQ_N * DIM];
__device__ __half g_wqT [DIM * DIM];
__device__ __half g_wkvT[2 * DIM * DIM];
__device__ __half g_woT [DIM * DIM];
__device__ __half g_w1T [DFF_ * DIM];
__device__ __half g_w2T [DIM * DFF_];

// ---------------------------------------------------------------------------
// Helpers
// ---------------------------------------------------------------------------
__device__ __forceinline__ uint32_t pk2(float a, float b) {
    __half2 h = __floats2half2_rn(a, b);
    return *reinterpret_cast<uint32_t*>(&h);
}
__device__ __forceinline__ void mma16(float* c, const uint32_t* a, const uint32_t* b) {
    asm volatile(
        "mma.sync.aligned.m16n8k16.row.col.f32.f16.f16.f32 "
        "{%0,%1,%2,%3}, {%4,%5,%6,%7}, {%8,%9}, {%0,%1,%2,%3};"
        : "+f"(c[0]), "+f"(c[1]), "+f"(c[2]), "+f"(c[3])
        : "r"(a[0]), "r"(a[1]), "r"(a[2]), "r"(a[3]), "r"(b[0]), "r"(b[1]));
}
__device__ __forceinline__ void ldsm4(uint32_t* r, uint32_t addr) {
    asm volatile("ldmatrix.sync.aligned.m8n8.x4.shared.b16 {%0,%1,%2,%3}, [%4];"
                 : "=r"(r[0]), "=r"(r[1]), "=r"(r[2]), "=r"(r[3]) : "r"(addr));
}
__device__ __forceinline__ void ldsm4t(uint32_t* r, uint32_t addr) {
    asm volatile("ldmatrix.sync.aligned.m8n8.x4.trans.shared.b16 {%0,%1,%2,%3}, [%4];"
                 : "=r"(r[0]), "=r"(r[1]), "=r"(r[2]), "=r"(r[3]) : "r"(addr));
}
__device__ __forceinline__ void cp16(uint32_t saddr, const void* g) {
    asm volatile("cp.async.cg.shared.global [%0], [%1], 16;" :: "r"(saddr), "l"(g));
}
__device__ __forceinline__ void cp_commit() {
    asm volatile("cp.async.commit_group;" ::: "memory");
}
template <int NN>
__device__ __forceinline__ void cp_wait() {
    asm volatile("cp.async.wait_group %0;" :: "n"(NN) : "memory");
}

// ---------------------------------------------------------------------------
// Weight transpose + fp16
// ---------------------------------------------------------------------------
__global__ void __launch_bounds__(256)
transpose_h_kernel(const float* __restrict__ in, __half* __restrict__ out, int K, int N)
{
    __shared__ float t[32][33];
    const int bx = blockIdx.x * 32;
    const int by = blockIdx.y * 32;
    const int x = threadIdx.x & 31;
    const int y = threadIdx.x >> 5;
#pragma unroll
    for (int i = 0; i < 32; i += 8)
        t[y + i][x] = in[(size_t)(by + y + i) * N + bx + x];
    __syncthreads();
#pragma unroll
    for (int i = 0; i < 32; i += 8)
        out[(size_t)(bx + y + i) * K + by + x] = __float2half_rn(t[x][y + i]);
}

// ---------------------------------------------------------------------------
// GEMM core (tile 128x128, K-chunk 32, 128 threads, cp.async 3 stage)
// ---------------------------------------------------------------------------
#define ABYTES 10240
#define STAGE_B (2 * ABYTES)
#define GEMM_SMEM (3 * STAGE_B)

struct GemmCtx {
    uint32_t smemU;
    int lane, g, tg, warp_m, warp_n, crow, cq;
    int arow, acol, brow, bcol;
};
__device__ __forceinline__ GemmCtx gemm_ctx(uint32_t smemU) {
    GemmCtx c;
    const int tid = threadIdx.x;
    c.smemU = smemU;
    c.lane = tid & 31;
    const int wid = tid >> 5;
    c.g = c.lane >> 2; c.tg = c.lane & 3;
    c.warp_m = wid >> 1; c.warp_n = wid & 1;
    c.crow = tid >> 2; c.cq = tid & 3;
    c.arow = c.lane & 15;
    c.acol = (c.lane >> 4) * 8;
    c.brow = (c.lane & 7) + ((c.lane >> 4) & 1) * 8;
    c.bcol = ((c.lane >> 3) & 1) * 8;
    return c;
}

__device__ __forceinline__ void gemm_issue(const GemmCtx& c, const __half* Ah,
                                           const __half* Bt, int tileM, int tileN,
                                           int K, int chunk, int stage) {
    const uint32_t base = c.smemU + stage * STAGE_B;
    const size_t koff = (size_t)chunk * 32 + c.cq * 8;
#pragma unroll
    for (int rr = 0; rr < 4; rr++) {
        const int row = c.crow + rr * 32;
        cp16(base + row * 80 + c.cq * 16, Ah + (size_t)(tileM + row) * K + koff);
        cp16(base + ABYTES + row * 80 + c.cq * 16, Bt + (size_t)(tileN + row) * K + koff);
    }
    cp_commit();
}

// consumer inner step shared by all GEMM variants
__device__ __forceinline__ void gemm_consume(const GemmCtx& c, int stage,
                                             float acc[4][8][4]) {
    const uint32_t aBase = c.smemU + stage * STAGE_B;
    const uint32_t bBase = aBase + ABYTES;
#pragma unroll
    for (int kk = 0; kk < 32; kk += 16) {
        uint32_t af[4][4];
        uint32_t bf[4][4];
#pragma unroll
        for (int mt = 0; mt < 4; mt++)
            ldsm4(af[mt], aBase + (c.warp_m * 64 + mt * 16 + c.arow) * 80
                          + (kk + c.acol) * 2);
#pragma unroll
        for (int p = 0; p < 4; p++)
            ldsm4(bf[p], bBase + (c.warp_n * 64 + p * 16 + c.brow) * 80
                         + (kk + c.bcol) * 2);
#pragma unroll
        for (int mt = 0; mt < 4; mt++)
#pragma unroll
            for (int nt = 0; nt < 8; nt++)
                mma16(acc[mt][nt], af[mt], &bf[nt >> 1][(nt & 1) * 2]);
    }
}

__device__ __forceinline__ void gemm_main(const GemmCtx& c, const __half* Ah,
                                          const __half* Bt, int tileM, int tileN,
                                          int K, float acc[4][8][4]) {
#pragma unroll
    for (int i = 0; i < 4; i++)
#pragma unroll
        for (int j = 0; j < 8; j++)
#pragma unroll
            for (int l = 0; l < 4; l++) acc[i][j][l] = 0.0f;

    const int NKC = K / 32;
    gemm_issue(c, Ah, Bt, tileM, tileN, K, 0, 0);
    if (NKC > 1) gemm_issue(c, Ah, Bt, tileM, tileN, K, 1, 1);

    for (int kc = 0; kc < NKC; kc++) {
        const int s = kc % 3;
        if (kc < NKC - 1) cp_wait<1>(); else cp_wait<0>();
        __syncthreads();
        if (kc + 2 < NKC) gemm_issue(c, Ah, Bt, tileM, tileN, K, kc + 2, (kc + 2) % 3);
        gemm_consume(c, s, acc);
    }
}

// ---------------------------------------------------------------------------
// Merged QKV projection with FUSED fp32->fp16 A conversion.
// 640 tiles: idx<512 -> KV [4096,2048]; else Q [2048,1024]. K = DIM.
// A producer: LDG.128 float x2 -> pack -> STS.128 (same stage slot as cp.async;
// ordering guaranteed by the pipeline's __syncthreads). B via cp.async.
// ---------------------------------------------------------------------------
__global__ void __launch_bounds__(128)
qkv_gemm(const float* __restrict__ x, const float* __restrict__ ctx,
         const __half* __restrict__ wqT, const __half* __restrict__ wkvT,
         const float* __restrict__ bq, const float* __restrict__ bkv,
         __half* __restrict__ qh, __half* __restrict__ kvh, float alphaQ)
{
    extern __shared__ __half smem_h[];
    GemmCtx c = gemm_ctx((uint32_t)__cvta_generic_to_shared(smem_h));

    const int idx = blockIdx.x;
    int tileM, tileN, N;
    const __half* Bt;
    const float* bias;
    __half* Ch;
    float alpha;
    if (idx < 512) {
        tileM = (idx >> 4) * 128; tileN = (idx & 15) * 128;
        N = 2 * DIM; Bt = wkvT; bias = bkv; Ch = kvh; alpha = 1.0f;
    } else {
        const int q = idx - 512;
        tileM = (q >> 3) * 128; tileN = (q & 7) * 128;
        N = DIM; Bt = wqT; bias = bq; Ch = qh; alpha = alphaQ;
    }
    // A float source for this tile (tiles never straddle the x/ctx boundary)
    const float* Af = (tileM < SEQ_N) ? x + (size_t)tileM * DIM
                                      : ctx + (size_t)(tileM - SEQ_N) * DIM;

    auto issue = [&](int chunk, int stage) {
        const uint32_t base = c.smemU + stage * STAGE_B;
        const int koff = chunk * 32 + c.cq * 8;
        // B via cp.async
#pragma unroll
        for (int rr = 0; rr < 4; rr++) {
            const int row = c.crow + rr * 32;
            cp16(base + ABYTES + row * 80 + c.cq * 16,
                 Bt + (size_t)(tileN + row) * DIM + koff);
        }
        cp_commit();
        // A: float load + convert + STS
        __half* sA = smem_h + stage * (STAGE_B / 2);
#pragma unroll
        for (int rr = 0; rr < 4; rr++) {
            const int row = c.crow + rr * 32;
            const float* src = Af + (size_t)row * DIM + koff;
            const float4 a = *reinterpret_cast<const float4*>(src);
            const float4 b = *reinterpret_cast<const float4*>(src + 4);
            uint4 h;
            h.x = pk2(a.x, a.y); h.y = pk2(a.z, a.w);
            h.z = pk2(b.x, b.y); h.w = pk2(b.z, b.w);
            *reinterpret_cast<uint4*>(sA + row * 40 + c.cq * 8) = h;
        }
    };

    float acc[4][8][4];
#pragma unroll
    for (int i = 0; i < 4; i++)
#pragma unroll
        for (int j = 0; j < 8; j++)
#pragma unroll
            for (int l = 0; l < 4; l++) acc[i][j][l] = 0.0f;

    const int NKC = DIM / 32;
    issue(0, 0);
    issue(1, 1);
    for (int kc = 0; kc < NKC; kc++) {
        const int s = kc % 3;
        if (kc < NKC - 1) cp_wait<1>(); else cp_wait<0>();
        __syncthreads();
        if (kc + 2 < NKC) issue(kc + 2, (kc + 2) % 3);
        gemm_consume(c, s, acc);
    }

#pragma unroll
    for (int mt = 0; mt < 4; mt++) {
        const int r0 = tileM + c.warp_m * 64 + mt * 16 + c.g;
#pragma unroll
        for (int nt = 0; nt < 8; nt++) {
            const int col = tileN + c.warp_n * 64 + nt * 8 + c.tg * 2;
            const float2 bv = *reinterpret_cast<const float2*>(bias + col);
#pragma unroll
            for (int hh = 0; hh < 2; hh++) {
                const int r = r0 + hh * 8;
                const float v0 = (acc[mt][nt][hh * 2 + 0] + bv.x) * alpha;
                const float v1 = (acc[mt][nt][hh * 2 + 1] + bv.y) * alpha;
                *reinterpret_cast<uint32_t*>(Ch + (size_t)r * N + col) = pk2(v0, v1);
            }
        }
    }
}

// ---------------------------------------------------------------------------
// General GEMM: EPI 2: half gelu(acc+bias); EPI 3: float acc+bias+resid
// ---------------------------------------------------------------------------
template <int EPI>
__global__ void __launch_bounds__(128)
mma_gemm(const __half* __restrict__ Ah, const __half* __restrict__ Bt,
         const float* __restrict__ bias, const float* __restrict__ resid,
         float* __restrict__ Cf, __half* __restrict__ Ch,
         int N, int K)
{
    extern __shared__ __half smem_h[];
    GemmCtx c = gemm_ctx((uint32_t)__cvta_generic_to_shared(smem_h));

    const int tileM = blockIdx.y * 128;
    const int tileN = blockIdx.x * 128;

    float acc[4][8][4];
    gemm_main(c, Ah, Bt, tileM, tileN, K, acc);

#pragma unroll
    for (int mt = 0; mt < 4; mt++) {
        const int r0 = tileM + c.warp_m * 64 + mt * 16 + c.g;
#pragma unroll
        for (int nt = 0; nt < 8; nt++) {
            const int col = tileN + c.warp_n * 64 + nt * 8 + c.tg * 2;
            const float2 bv = *reinterpret_cast<const float2*>(bias + col);
#pragma unroll
            for (int hh = 0; hh < 2; hh++) {
                const int r = r0 + hh * 8;
                float v0 = acc[mt][nt][hh * 2 + 0] + bv.x;
                float v1 = acc[mt][nt][hh * 2 + 1] + bv.y;
                if (EPI == 2) {
                    v0 = 0.5f * v0 * (1.0f + erff(v0 * 0.70710678118654752f));
                    v1 = 0.5f * v1 * (1.0f + erff(v1 * 0.70710678118654752f));
                    *reinterpret_cast<uint32_t*>(Ch + (size_t)r * N + col) = pk2(v0, v1);
                } else {
                    const float2 rv = *reinterpret_cast<const float2*>(
                        resid + (size_t)r * N + col);
                    float2 o; o.x = v0 + rv.x; o.y = v1 + rv.y;
                    *reinterpret_cast<float2*>(Cf + (size_t)r * N + col) = o;
                }
            }
        }
    }
}

// ---------------------------------------------------------------------------
// Flash attention: QROWS=128, 256 threads, single 256-CTA launch,
// HEAVY TILES FIRST (blockIdx.x reversed). cp.async double-buffered K/V.
// ---------------------------------------------------------------------------
#define QROWS 128
#define HS 72
#define AQ_QS 0
#define AQ_K0 (QROWS * HS)               // 9216
#define AQ_PS (AQ_K0 + 4 * 64 * HS)      // 27648
#define AQ_HALFS (AQ_PS + QROWS * HS)    // 36864
#define ATT_SMEM (AQ_HALFS * 2)          // 73728 B

__global__ void __launch_bounds__(256)
attn_kernel(const __half* __restrict__ Qh,
            const __half* __restrict__ KVh,
            __half* __restrict__ Oh)
{
    extern __shared__ __half smh[];
    const uint32_t uBase = (uint32_t)__cvta_generic_to_shared(smh);
    const uint32_t uQs = uBase;
    const uint32_t uPs = uBase + AQ_PS * 2;

    const int h   = blockIdx.y;
    // reversed: largest q0 (most causal work) scheduled first
    const int q0  = (gridDim.x - 1 - blockIdx.x) * QROWS;
    const int tid = threadIdx.x;
    const int wid = tid >> 5;
    const int lane = tid & 31;
    const int g   = lane >> 2;
    const int tg  = lane & 3;
    const int wq0 = wid * 16;

    __half* Qs = smh + AQ_QS;
    for (int e = tid; e < QROWS * 8; e += 256) {
        const int row = e >> 3, cc = e & 7;
        *reinterpret_cast<uint4*>(&Qs[row * HS + cc * 8]) =
            *reinterpret_cast<const uint4*>(Qh + (size_t)(q0 + row) * DIM + h * DH + cc * 8);
    }

    float m0 = -1e30f, m1 = -1e30f, l0 = 0.0f, l1 = 0.0f;
    float accO[8][4];
#pragma unroll
    for (int nt = 0; nt < 8; nt++)
#pragma unroll
        for (int i = 0; i < 4; i++) accO[nt][i] = 0.0f;

    const int prow = tid >> 3, pcc = tid & 7;
    auto issue_kv = [&](int j, int s) {
        const uint32_t uK = uBase + (AQ_K0 + s * 2 * 64 * HS) * 2;
        const uint32_t uV = uK + 64 * HS * 2;
#pragma unroll
        for (int rr = 0; rr < 64; rr += 32) {
            const __half* src = KVh + (size_t)(j + prow + rr) * (2 * DIM) + h * DH + pcc * 8;
            cp16(uK + (prow + rr) * (HS * 2) + pcc * 16, src);
            cp16(uV + (prow + rr) * (HS * 2) + pcc * 16, src + DIM);
        }
        cp_commit();
    };

    const int gq0 = q0 + wq0 + g;
    const int gq1 = gq0 + 8;

    const int arow = lane & 15;
    const int acol = (lane >> 4) * 8;
    const int brow = (lane & 7) + ((lane >> 4) & 1) * 8;
    const int bcol = ((lane >> 3) & 1) * 8;
    const int vkrow = (lane & 7) + ((lane >> 3) & 1) * 8;
    const int vncol = ((lane >> 4) & 1) * 8;

    int j0 = 0;
    int stage = 0;
    issue_kv(0, 0);
    while (j0 < TOTK) {
        int nj = j0 + 64;
        if (nj >= q0 + QROWS && nj < SEQ_N) nj = SEQ_N;  // causal tile skip

        __syncthreads();
        if (nj < TOTK) {
            issue_kv(nj, stage ^ 1);
            cp_wait<1>();
        } else {
            cp_wait<0>();
        }
        __syncthreads();

        const uint32_t uKs = uBase + (AQ_K0 + stage * 2 * 64 * HS) * 2;
        const uint32_t uVs = uKs + 64 * HS * 2;

        float s[8][4];
#pragma unroll
        for (int nt = 0; nt < 8; nt++)
#pragma unroll
            for (int i = 0; i < 4; i++) s[nt][i] = 0.0f;
#pragma unroll
        for (int kf = 0; kf < 4; kf++) {
            const int kk = kf * 16;
            uint32_t a[4];
            ldsm4(a, uQs + (wq0 + arow) * (HS * 2) + (kk + acol) * 2);
            uint32_t bf[4][4];
#pragma unroll
            for (int p = 0; p < 4; p++)
                ldsm4(bf[p], uKs + (p * 16 + brow) * (HS * 2) + (kk + bcol) * 2);
#pragma unroll
            for (int nt = 0; nt < 8; nt++)
                mma16(s[nt], a, &bf[nt >> 1][(nt & 1) * 2]);
        }

        if (j0 < SEQ_N) {
#pragma unroll
            for (int nt = 0; nt < 8; nt++) {
                const int gk = j0 + nt * 8 + 2 * tg;
                if (gk > gq0)     s[nt][0] = MASK_VAL;
                if (gk + 1 > gq0) s[nt][1] = MASK_VAL;
                if (gk > gq1)     s[nt][2] = MASK_VAL;
                if (gk + 1 > gq1) s[nt][3] = MASK_VAL;
            }
        }

        float mx0 = -1e30f, mx1 = -1e30f;
#pragma unroll
        for (int nt = 0; nt < 8; nt++) {
            mx0 = fmaxf(mx0, fmaxf(s[nt][0], s[nt][1]));
            mx1 = fmaxf(mx1, fmaxf(s[nt][2], s[nt][3]));
        }
        mx0 = fmaxf(mx0, __shfl_xor_sync(0xffffffffu, mx0, 1));
        mx0 = fmaxf(mx0, __shfl_xor_sync(0xffffffffu, mx0, 2));
        mx1 = fmaxf(mx1, __shfl_xor_sync(0xffffffffu, mx1, 1));
        mx1 = fmaxf(mx1, __shfl_xor_sync(0xffffffffu, mx1, 2));
        const float mn0 = fmaxf(m0, mx0);
        const float mn1 = fmaxf(m1, mx1);
        const float fac0 = exp2f(m0 - mn0);
        const float fac1 = exp2f(m1 - mn1);
        float sum0 = 0.0f, sum1 = 0.0f;
#pragma unroll
        for (int nt = 0; nt < 8; nt++) {
            s[nt][0] = exp2f(s[nt][0] - mn0);
            s[nt][1] = exp2f(s[nt][1] - mn0);
            s[nt][2] = exp2f(s[nt][2] - mn1);
            s[nt][3] = exp2f(s[nt][3] - mn1);
            sum0 += s[nt][0] + s[nt][1];
            sum1 += s[nt][2] + s[nt][3];
        }
        sum0 += __shfl_xor_sync(0xffffffffu, sum0, 1);
        sum0 += __shfl_xor_sync(0xffffffffu, sum0, 2);
        sum1 += __shfl_xor_sync(0xffffffffu, sum1, 1);
        sum1 += __shfl_xor_sync(0xffffffffu, sum1, 2);
        l0 = l0 * fac0 + sum0;
        l1 = l1 * fac1 + sum1;
        m0 = mn0; m1 = mn1;
#pragma unroll
        for (int nt = 0; nt < 8; nt++) {
            accO[nt][0] *= fac0; accO[nt][1] *= fac0;
            accO[nt][2] *= fac1; accO[nt][3] *= fac1;
        }
        __half* Ps = smh + AQ_PS;
#pragma unroll
        for (int nt = 0; nt < 8; nt++) {
            *reinterpret_cast<uint32_t*>(&Ps[(wq0 + g) * HS + nt * 8 + 2 * tg]) =
                pk2(s[nt][0], s[nt][1]);
            *reinterpret_cast<uint32_t*>(&Ps[(wq0 + g + 8) * HS + nt * 8 + 2 * tg]) =
                pk2(s[nt][2], s[nt][3]);
        }
        __syncwarp();

#pragma unroll
        for (int kf = 0; kf < 4; kf++) {
            const int kk = kf * 16;
            uint32_t a[4];
            ldsm4(a, uPs + (wq0 + arow) * (HS * 2) + (kk + acol) * 2);
            uint32_t bf[4][4];
#pragma unroll
            for (int p = 0; p < 4; p++)
                ldsm4t(bf[p], uVs + (kk + vkrow) * (HS * 2) + (p * 16 + vncol) * 2);
#pragma unroll
            for (int nt = 0; nt < 8; nt++)
                mma16(accO[nt], a, &bf[nt >> 1][(nt & 1) * 2]);
        }
        stage ^= 1;
        j0 = nj;
    }

    const float inv0 = 1.0f / l0;
    const float inv1 = 1.0f / l1;
#pragma unroll
    for (int nt = 0; nt < 8; nt++) {
        const int col = h * DH + nt * 8 + 2 * tg;
        *reinterpret_cast<uint32_t*>(Oh + (size_t)gq0 * DIM + col) =
            pk2(accO[nt][0] * inv0, accO[nt][1] * inv0);
        *reinterpret_cast<uint32_t*>(Oh + (size_t)gq1 * DIM + col) =
            pk2(accO[nt][2] * inv1, accO[nt][3] * inv1);
    }
}

// ---------------------------------------------------------------------------
// LayerNorm (vectorized)
// ---------------------------------------------------------------------------
template <bool WH>
__global__ void __launch_bounds__(256)
ln_kernel(const float* __restrict__ a, const float* __restrict__ g,
          const float* __restrict__ beta, float* __restrict__ out,
          __half* __restrict__ outh)
{
    const int row = blockIdx.x;
    const int c0 = threadIdx.x * 4;
    __shared__ float sh1[8], sh2[8];

    const float4 v = *reinterpret_cast<const float4*>(a + (size_t)row * DIM + c0);
    float s = v.x + v.y + v.z + v.w;
#pragma unroll
    for (int off = 16; off >= 1; off >>= 1) s += __shfl_xor_sync(0xffffffffu, s, off);
    if ((threadIdx.x & 31) == 0) sh1[threadIdx.x >> 5] = s;
    __syncthreads();
    float mu = 0.0f;
#pragma unroll
    for (int i = 0; i < 8; i++) mu += sh1[i];
    mu *= (1.0f / DIM);

    float d0 = v.x - mu, d1 = v.y - mu, d2 = v.z - mu, d3 = v.w - mu;
    float vs = d0 * d0 + d1 * d1 + d2 * d2 + d3 * d3;
#pragma unroll
    for (int off = 16; off >= 1; off >>= 1) vs += __shfl_xor_sync(0xffffffffu, vs, off);
    if ((threadIdx.x & 31) == 0) sh2[threadIdx.x >> 5] = vs;
    __syncthreads();
    float var = 0.0f;
#pragma unroll
    for (int i = 0; i < 8; i++) var += sh2[i];
    const float inv = rsqrtf(var * (1.0f / DIM) + 1e-5f);

    const float4 gv = *reinterpret_cast<const float4*>(g + c0);
    const float4 bv = *reinterpret_cast<const float4*>(beta + c0);
    float4 o;
    o.x = d0 * inv * gv.x + bv.x;
    o.y = d1 * inv * gv.y + bv.y;
    o.z = d2 * inv * gv.z + bv.z;
    o.w = d3 * inv * gv.w + bv.w;
    *reinterpret_cast<float4*>(out + (size_t)row * DIM + c0) = o;
    if (WH) {
        uint2 ho; ho.x = pk2(o.x, o.y); ho.y = pk2(o.z, o.w);
        *reinterpret_cast<uint2*>(outh + (size_t)row * DIM + c0) = ho;
    }
}

// ---------------------------------------------------------------------------
// Launch (single-stream chain; weight-prep fork on s2)
// ---------------------------------------------------------------------------
extern "C" void kernel_launch(void* const* d_in, const int* in_sizes, int n_in,
                              void* d_out, int out_size)
{
    const float* x     = (const float*)d_in[0];
    const float* ctx   = (const float*)d_in[1];
    const float* Wq    = (const float*)d_in[2];
    const float* bq    = (const float*)d_in[3];
    const float* Wkv   = (const float*)d_in[4];
    const float* bkv   = (const float*)d_in[5];
    const float* Wo    = (const float*)d_in[6];
    const float* bo    = (const float*)d_in[7];
    const float* ln1g  = (const float*)d_in[8];
    const float* ln1b  = (const float*)d_in[9];
    const float* W1    = (const float*)d_in[10];
    const float* bf1   = (const float*)d_in[11];
    const float* W2    = (const float*)d_in[12];
    const float* bf2   = (const float*)d_in[13];
    const float* ln2g  = (const float*)d_in[14];
    const float* ln2b  = (const float*)d_in[15];
    float* out = (float*)d_out;

    __half *qh, *kvh, *attnh, *x1h, *ffh, *wqT, *wkvT, *woT, *w1T, *w2T;
    float *t, *x1;
    cudaGetSymbolAddress((void**)&qh,    g_qh);
    cudaGetSymbolAddress((void**)&kvh,   g_kvh);
    cudaGetSymbolAddress((void**)&attnh, g_attnh);
    cudaGetSymbolAddress((void**)&x1h,   g_x1h);
    cudaGetSymbolAddress((void**)&ffh,   g_ffh);
    cudaGetSymbolAddress((void**)&t,     g_t);
    cudaGetSymbolAddress((void**)&x1,    g_x1);
    cudaGetSymbolAddress((void**)&wqT,   g_wqT);
    cudaGetSymbolAddress((void**)&wkvT,  g_wkvT);
    cudaGetSymbolAddress((void**)&woT,   g_woT);
    cudaGetSymbolAddress((void**)&w1T,   g_w1T);
    cudaGetSymbolAddress((void**)&w2T,   g_w2T);

    cudaFuncSetAttribute(attn_kernel, cudaFuncAttributeMaxDynamicSharedMemorySize, ATT_SMEM);
    cudaFuncSetAttribute(qkv_gemm,    cudaFuncAttributeMaxDynamicSharedMemorySize, GEMM_SMEM);
    cudaFuncSetAttribute(mma_gemm<2>, cudaFuncAttributeMaxDynamicSharedMemorySize, GEMM_SMEM);
    cudaFuncSetAttribute(mma_gemm<3>, cudaFuncAttributeMaxDynamicSharedMemorySize, GEMM_SMEM);

    static cudaStream_t s2 = nullptr;
    static cudaEvent_t eBegin = nullptr, eQKVw = nullptr, eW = nullptr;
    if (s2 == nullptr) {
        cudaStreamCreateWithFlags(&s2, cudaStreamNonBlocking);
        cudaEventCreateWithFlags(&eBegin, cudaEventDisableTiming);
        cudaEventCreateWithFlags(&eQKVw,  cudaEventDisableTiming);
        cudaEventCreateWithFlags(&eW,     cudaEventDisableTiming);
    }

    // ---- fork: weight transposes on s2 ----
    cudaEventRecord(eBegin, 0);
    cudaStreamWaitEvent(s2, eBegin, 0);
    transpose_h_kernel<<<dim3(DIM / 32, DIM / 32), 256, 0, s2>>>(Wq,  wqT,  DIM,  DIM);
    transpose_h_kernel<<<dim3(2 * DIM / 32, DIM / 32), 256, 0, s2>>>(Wkv, wkvT, DIM, 2 * DIM);
    cudaEventRecord(eQKVw, s2);
    transpose_h_kernel<<<dim3(DIM / 32, DIM / 32), 256, 0, s2>>>(Wo,  woT,  DIM,  DIM);
    transpose_h_kernel<<<dim3(DFF_ / 32, DIM / 32), 256, 0, s2>>>(W1,  w1T,  DIM,  DFF_);
    transpose_h_kernel<<<dim3(DIM / 32, DFF_ / 32), 256, 0, s2>>>(W2,  w2T,  DFF_, DIM);
    cudaEventRecord(eW, s2);

    // 1+2) merged QKV projection with fused activation conversion
    cudaStreamWaitEvent(0, eQKVw, 0);
    qkv_gemm<<<640, 128, GEMM_SMEM>>>(x, ctx, wqT, wkvT, bq, bkv, qh, kvh,
                                      0.18033688011112042f);

    // 3) attention (heavy tiles first)
    attn_kernel<<<dim3(SEQ_N / QROWS, HEADS), 256, ATT_SMEM>>>(qh, kvh, attnh);

    // ---- join: remaining weights ready ----
    cudaStreamWaitEvent(0, eW, 0);

    // 4) t = attn @ Wo + bo + x
    mma_gemm<3><<<dim3(DIM / 128, SEQ_N / 128), 128, GEMM_SMEM>>>(
        attnh, woT, bo, x, t, nullptr, DIM, DIM);

    // 5) x1 = LN1(t)
    ln_kernel<true><<<SEQ_N, 256>>>(t, ln1g, ln1b, x1, x1h);

    // 6) ffh = gelu(x1 @ W1 + bf1)
    mma_gemm<2><<<dim3(DFF_ / 128, SEQ_N / 128), 128, GEMM_SMEM>>>(
        x1h, w1T, bf1, nullptr, nullptr, ffh, DFF_, DIM);

    // 7) t = ff @ W2 + bf2 + x1
    mma_gemm<3><<<dim3(DIM / 128, SEQ_N / 128), 128, GEMM_SMEM>>>(
        ffh, w2T, bf2, x1, t, nullptr, DIM, DFF_);

    // 8) out = LN2(t)
    ln_kernel<false><<<SEQ_N, 256>>>(t, ln2g, ln2b, out, nullptr);
}

// round 15
// speedup vs baseline: 1.0230x; 1.0230x over previous
#include <cuda_runtime.h>
#include <cuda_fp16.h>
#include <math.h>
#include <stdint.h>

// R15 = R11 (best measured config, 483us) with ONE delta: GEMM cp.async
// pipeline 3 -> 4 stages. R14's fused-convert producer regressed (sync LDG
// bubbles in async pipeline) and is reverted; convert kernel restored.

// ---------------------------------------------------------------------------
// Problem constants
// ---------------------------------------------------------------------------
#define SEQ_N 2048
#define SEQ_M 2048
#define TOTK  (SEQ_N + SEQ_M)   // 4096
#define DIM   1024
#define HEADS 16
#define DH    64
#define DFF_  4096
#define MASK_VAL (-50000.0f)

// ---------------------------------------------------------------------------
// Scratch (device globals; no allocation allowed)
// ---------------------------------------------------------------------------
__device__ __half g_inh [TOTK * DIM];
__device__ __half g_qh  [SEQ_N * DIM];
__device__ __half g_kvh [TOTK * 2 * DIM];
__device__ __half g_attnh[SEQ_N * DIM];
__device__ __half g_x1h [SEQ_N * DIM];
__device__ __half g_ffh [SEQ_N * DFF_];
__device__ float  g_t   [SEQ_N * DIM];
__device__ float  g_x1  [SEQ_N * DIM];
__device__ __half g_wqT [DIM * DIM];
__device__ __half g_wkvT[2 * DIM * DIM];
__device__ __half g_woT [DIM * DIM];
__device__ __half g_w1T [DFF_ * DIM];
__device__ __half g_w2T [DIM * DFF_];

// ---------------------------------------------------------------------------
// Helpers
// ---------------------------------------------------------------------------
__device__ __forceinline__ uint32_t pk2(float a, float b) {
    __half2 h = __floats2half2_rn(a, b);
    return *reinterpret_cast<uint32_t*>(&h);
}
__device__ __forceinline__ void mma16(float* c, const uint32_t* a, const uint32_t* b) {
    asm volatile(
        "mma.sync.aligned.m16n8k16.row.col.f32.f16.f16.f32 "
        "{%0,%1,%2,%3}, {%4,%5,%6,%7}, {%8,%9}, {%0,%1,%2,%3};"
        : "+f"(c[0]), "+f"(c[1]), "+f"(c[2]), "+f"(c[3])
        : "r"(a[0]), "r"(a[1]), "r"(a[2]), "r"(a[3]), "r"(b[0]), "r"(b[1]));
}
__device__ __forceinline__ void ldsm4(uint32_t* r, uint32_t addr) {
    asm volatile("ldmatrix.sync.aligned.m8n8.x4.shared.b16 {%0,%1,%2,%3}, [%4];"
                 : "=r"(r[0]), "=r"(r[1]), "=r"(r[2]), "=r"(r[3]) : "r"(addr));
}
__device__ __forceinline__ void ldsm4t(uint32_t* r, uint32_t addr) {
    asm volatile("ldmatrix.sync.aligned.m8n8.x4.trans.shared.b16 {%0,%1,%2,%3}, [%4];"
                 : "=r"(r[0]), "=r"(r[1]), "=r"(r[2]), "=r"(r[3]) : "r"(addr));
}
__device__ __forceinline__ void cp16(uint32_t saddr, const void* g) {
    asm volatile("cp.async.cg.shared.global [%0], [%1], 16;" :: "r"(saddr), "l"(g));
}
__device__ __forceinline__ void cp_commit() {
    asm volatile("cp.async.commit_group;" ::: "memory");
}
template <int NN>
__device__ __forceinline__ void cp_wait() {
    asm volatile("cp.async.wait_group %0;" :: "n"(NN) : "memory");
}

// ---------------------------------------------------------------------------
// convert concat(x, ctx) -> fp16 g_inh
// ---------------------------------------------------------------------------
__global__ void __launch_bounds__(256)
convert_h_kernel(const float* __restrict__ x, const float* __restrict__ ctx,
                 __half* __restrict__ out)
{
    const size_t i = ((size_t)blockIdx.x * 256 + threadIdx.x) * 8;
    const float* src = (i < (size_t)SEQ_N * DIM) ? x + i
                                                 : ctx + (i - (size_t)SEQ_N * DIM);
    const float4 a = *reinterpret_cast<const float4*>(src);
    const float4 b = *reinterpret_cast<const float4*>(src + 4);
    uint4 o;
    o.x = pk2(a.x, a.y); o.y = pk2(a.z, a.w);
    o.z = pk2(b.x, b.y); o.w = pk2(b.z, b.w);
    *reinterpret_cast<uint4*>(out + i) = o;
}

// ---------------------------------------------------------------------------
// Weight transpose + fp16
// ---------------------------------------------------------------------------
__global__ void __launch_bounds__(256)
transpose_h_kernel(const float* __restrict__ in, __half* __restrict__ out, int K, int N)
{
    __shared__ float t[32][33];
    const int bx = blockIdx.x * 32;
    const int by = blockIdx.y * 32;
    const int x = threadIdx.x & 31;
    const int y = threadIdx.x >> 5;
#pragma unroll
    for (int i = 0; i < 32; i += 8)
        t[y + i][x] = in[(size_t)(by + y + i) * N + bx + x];
    __syncthreads();
#pragma unroll
    for (int i = 0; i < 32; i += 8)
        out[(size_t)(bx + y + i) * K + by + x] = __float2half_rn(t[x][y + i]);
}

// ---------------------------------------------------------------------------
// GEMM core (tile 128x128, K-chunk 32, 128 threads, cp.async FOUR stages)
// ---------------------------------------------------------------------------
#define ABYTES 10240
#define STAGE_B (2 * ABYTES)
#define GSTAGES 4
#define GEMM_SMEM (GSTAGES * STAGE_B)   // 81920 B

struct GemmCtx {
    uint32_t smemU;
    int lane, g, tg, warp_m, warp_n, crow, cq;
    int arow, acol, brow, bcol;
};
__device__ __forceinline__ GemmCtx gemm_ctx(uint32_t smemU) {
    GemmCtx c;
    const int tid = threadIdx.x;
    c.smemU = smemU;
    c.lane = tid & 31;
    const int wid = tid >> 5;
    c.g = c.lane >> 2; c.tg = c.lane & 3;
    c.warp_m = wid >> 1; c.warp_n = wid & 1;
    c.crow = tid >> 2; c.cq = tid & 3;
    c.arow = c.lane & 15;
    c.acol = (c.lane >> 4) * 8;
    c.brow = (c.lane & 7) + ((c.lane >> 4) & 1) * 8;
    c.bcol = ((c.lane >> 3) & 1) * 8;
    return c;
}

__device__ __forceinline__ void gemm_issue(const GemmCtx& c, const __half* Ah,
                                           const __half* Bt, int tileM, int tileN,
                                           int K, int chunk, int stage) {
    const uint32_t base = c.smemU + stage * STAGE_B;
    const size_t koff = (size_t)chunk * 32 + c.cq * 8;
#pragma unroll
    for (int rr = 0; rr < 4; rr++) {
        const int row = c.crow + rr * 32;
        cp16(base + row * 80 + c.cq * 16, Ah + (size_t)(tileM + row) * K + koff);
        cp16(base + ABYTES + row * 80 + c.cq * 16, Bt + (size_t)(tileN + row) * K + koff);
    }
    cp_commit();
}

__device__ __forceinline__ void gemm_consume(const GemmCtx& c, int stage,
                                             float acc[4][8][4]) {
    const uint32_t aBase = c.smemU + stage * STAGE_B;
    const uint32_t bBase = aBase + ABYTES;
#pragma unroll
    for (int kk = 0; kk < 32; kk += 16) {
        uint32_t af[4][4];
        uint32_t bf[4][4];
#pragma unroll
        for (int mt = 0; mt < 4; mt++)
            ldsm4(af[mt], aBase + (c.warp_m * 64 + mt * 16 + c.arow) * 80
                          + (kk + c.acol) * 2);
#pragma unroll
        for (int p = 0; p < 4; p++)
            ldsm4(bf[p], bBase + (c.warp_n * 64 + p * 16 + c.brow) * 80
                         + (kk + c.bcol) * 2);
#pragma unroll
        for (int mt = 0; mt < 4; mt++)
#pragma unroll
            for (int nt = 0; nt < 8; nt++)
                mma16(acc[mt][nt], af[mt], &bf[nt >> 1][(nt & 1) * 2]);
    }
}

__device__ __forceinline__ void gemm_main(const GemmCtx& c, const __half* Ah,
                                          const __half* Bt, int tileM, int tileN,
                                          int K, float acc[4][8][4]) {
#pragma unroll
    for (int i = 0; i < 4; i++)
#pragma unroll
        for (int j = 0; j < 8; j++)
#pragma unroll
            for (int l = 0; l < 4; l++) acc[i][j][l] = 0.0f;

    const int NKC = K / 32;   // >= 32 for all our GEMMs
    gemm_issue(c, Ah, Bt, tileM, tileN, K, 0, 0);
    gemm_issue(c, Ah, Bt, tileM, tileN, K, 1, 1);
    gemm_issue(c, Ah, Bt, tileM, tileN, K, 2, 2);

    for (int kc = 0; kc < NKC; kc++) {
        const int s = kc % GSTAGES;
        // ensure group kc complete: allow (issued - kc - 1) outstanding
        if (kc < NKC - 3)      cp_wait<2>();
        else if (kc == NKC - 3) cp_wait<2>();
        else if (kc == NKC - 2) cp_wait<1>();
        else                    cp_wait<0>();
        __syncthreads();
        if (kc + 3 < NKC)
            gemm_issue(c, Ah, Bt, tileM, tileN, K, kc + 3, (kc + 3) % GSTAGES);
        gemm_consume(c, s, acc);
    }
}

// ---------------------------------------------------------------------------
// Merged QKV projection: 640 tiles. idx<512 -> KV [4096,2048]; else Q.
// ---------------------------------------------------------------------------
__global__ void __launch_bounds__(128)
qkv_gemm(const __half* __restrict__ Ah,
         const __half* __restrict__ wqT, const __half* __restrict__ wkvT,
         const float* __restrict__ bq, const float* __restrict__ bkv,
         __half* __restrict__ qh, __half* __restrict__ kvh, float alphaQ)
{
    extern __shared__ __half smem_h[];
    GemmCtx c = gemm_ctx((uint32_t)__cvta_generic_to_shared(smem_h));

    const int idx = blockIdx.x;
    int tileM, tileN, N;
    const __half* Bt;
    const float* bias;
    __half* Ch;
    float alpha;
    if (idx < 512) {
        tileM = (idx >> 4) * 128; tileN = (idx & 15) * 128;
        N = 2 * DIM; Bt = wkvT; bias = bkv; Ch = kvh; alpha = 1.0f;
    } else {
        const int q = idx - 512;
        tileM = (q >> 3) * 128; tileN = (q & 7) * 128;
        N = DIM; Bt = wqT; bias = bq; Ch = qh; alpha = alphaQ;
    }

    float acc[4][8][4];
    gemm_main(c, Ah, Bt, tileM, tileN, DIM, acc);

#pragma unroll
    for (int mt = 0; mt < 4; mt++) {
        const int r0 = tileM + c.warp_m * 64 + mt * 16 + c.g;
#pragma unroll
        for (int nt = 0; nt < 8; nt++) {
            const int col = tileN + c.warp_n * 64 + nt * 8 + c.tg * 2;
            const float2 bv = *reinterpret_cast<const float2*>(bias + col);
#pragma unroll
            for (int hh = 0; hh < 2; hh++) {
                const int r = r0 + hh * 8;
                const float v0 = (acc[mt][nt][hh * 2 + 0] + bv.x) * alpha;
                const float v1 = (acc[mt][nt][hh * 2 + 1] + bv.y) * alpha;
                *reinterpret_cast<uint32_t*>(Ch + (size_t)r * N + col) = pk2(v0, v1);
            }
        }
    }
}

// ---------------------------------------------------------------------------
// General GEMM: EPI 2: half gelu(acc+bias); EPI 3: float acc+bias+resid
// ---------------------------------------------------------------------------
template <int EPI>
__global__ void __launch_bounds__(128)
mma_gemm(const __half* __restrict__ Ah, const __half* __restrict__ Bt,
         const float* __restrict__ bias, const float* __restrict__ resid,
         float* __restrict__ Cf, __half* __restrict__ Ch,
         int N, int K)
{
    extern __shared__ __half smem_h[];
    GemmCtx c = gemm_ctx((uint32_t)__cvta_generic_to_shared(smem_h));

    const int tileM = blockIdx.y * 128;
    const int tileN = blockIdx.x * 128;

    float acc[4][8][4];
    gemm_main(c, Ah, Bt, tileM, tileN, K, acc);

#pragma unroll
    for (int mt = 0; mt < 4; mt++) {
        const int r0 = tileM + c.warp_m * 64 + mt * 16 + c.g;
#pragma unroll
        for (int nt = 0; nt < 8; nt++) {
            const int col = tileN + c.warp_n * 64 + nt * 8 + c.tg * 2;
            const float2 bv = *reinterpret_cast<const float2*>(bias + col);
#pragma unroll
            for (int hh = 0; hh < 2; hh++) {
                const int r = r0 + hh * 8;
                float v0 = acc[mt][nt][hh * 2 + 0] + bv.x;
                float v1 = acc[mt][nt][hh * 2 + 1] + bv.y;
                if (EPI == 2) {
                    v0 = 0.5f * v0 * (1.0f + erff(v0 * 0.70710678118654752f));
                    v1 = 0.5f * v1 * (1.0f + erff(v1 * 0.70710678118654752f));
                    *reinterpret_cast<uint32_t*>(Ch + (size_t)r * N + col) = pk2(v0, v1);
                } else {
                    const float2 rv = *reinterpret_cast<const float2*>(
                        resid + (size_t)r * N + col);
                    float2 o; o.x = v0 + rv.x; o.y = v1 + rv.y;
                    *reinterpret_cast<float2*>(Cf + (size_t)r * N + col) = o;
                }
            }
        }
    }
}

// ---------------------------------------------------------------------------
// Flash attention (R11 version): QROWS=256, 512 threads, cp.async
// double-buffered K/V, V via ldmatrix.trans, exp2-domain softmax.
// ---------------------------------------------------------------------------
#define QROWS 256
#define HS 72
#define AQ_QS 0
#define AQ_K0 (QROWS * HS)               // 18432
#define AQ_PS (AQ_K0 + 4 * 64 * HS)      // 36864
#define AQ_HALFS (AQ_PS + QROWS * HS)    // 55296
#define ATT_SMEM (AQ_HALFS * 2)          // 110592 B

__global__ void __launch_bounds__(512)
attn_kernel(const __half* __restrict__ Qh,
            const __half* __restrict__ KVh,
            __half* __restrict__ Oh)
{
    extern __shared__ __half smh[];
    const uint32_t uBase = (uint32_t)__cvta_generic_to_shared(smh);
    const uint32_t uQs = uBase;
    const uint32_t uPs = uBase + AQ_PS * 2;

    const int h   = blockIdx.y;
    const int q0  = blockIdx.x * QROWS;
    const int tid = threadIdx.x;
    const int wid = tid >> 5;
    const int lane = tid & 31;
    const int g   = lane >> 2;
    const int tg  = lane & 3;
    const int wq0 = wid * 16;

    __half* Qs = smh + AQ_QS;
    for (int e = tid; e < QROWS * 8; e += 512) {
        const int row = e >> 3, cc = e & 7;
        *reinterpret_cast<uint4*>(&Qs[row * HS + cc * 8]) =
            *reinterpret_cast<const uint4*>(Qh + (size_t)(q0 + row) * DIM + h * DH + cc * 8);
    }

    float m0 = -1e30f, m1 = -1e30f, l0 = 0.0f, l1 = 0.0f;
    float accO[8][4];
#pragma unroll
    for (int nt = 0; nt < 8; nt++)
#pragma unroll
        for (int i = 0; i < 4; i++) accO[nt][i] = 0.0f;

    const int prow = tid >> 3, pcc = tid & 7;
    auto issue_kv = [&](int j, int s) {
        const uint32_t uK = uBase + (AQ_K0 + s * 2 * 64 * HS) * 2;
        const uint32_t uV = uK + 64 * HS * 2;
        const __half* src = KVh + (size_t)(j + prow) * (2 * DIM) + h * DH + pcc * 8;
        cp16(uK + prow * (HS * 2) + pcc * 16, src);
        cp16(uV + prow * (HS * 2) + pcc * 16, src + DIM);
        cp_commit();
    };

    const int gq0 = q0 + wq0 + g;
    const int gq1 = gq0 + 8;

    const int arow = lane & 15;
    const int acol = (lane >> 4) * 8;
    const int brow = (lane & 7) + ((lane >> 4) & 1) * 8;
    const int bcol = ((lane >> 3) & 1) * 8;
    const int vkrow = (lane & 7) + ((lane >> 3) & 1) * 8;
    const int vncol = ((lane >> 4) & 1) * 8;

    int j0 = 0;
    int stage = 0;
    issue_kv(0, 0);
    while (j0 < TOTK) {
        int nj = j0 + 64;
        if (nj >= q0 + QROWS && nj < SEQ_N) nj = SEQ_N;  // causal tile skip

        __syncthreads();
        if (nj < TOTK) {
            issue_kv(nj, stage ^ 1);
            cp_wait<1>();
        } else {
            cp_wait<0>();
        }
        __syncthreads();

        const uint32_t uKs = uBase + (AQ_K0 + stage * 2 * 64 * HS) * 2;
        const uint32_t uVs = uKs + 64 * HS * 2;

        float s[8][4];
#pragma unroll
        for (int nt = 0; nt < 8; nt++)
#pragma unroll
            for (int i = 0; i < 4; i++) s[nt][i] = 0.0f;
#pragma unroll
        for (int kf = 0; kf < 4; kf++) {
            const int kk = kf * 16;
            uint32_t a[4];
            ldsm4(a, uQs + (wq0 + arow) * (HS * 2) + (kk + acol) * 2);
            uint32_t bf[4][4];
#pragma unroll
            for (int p = 0; p < 4; p++)
                ldsm4(bf[p], uKs + (p * 16 + brow) * (HS * 2) + (kk + bcol) * 2);
#pragma unroll
            for (int nt = 0; nt < 8; nt++)
                mma16(s[nt], a, &bf[nt >> 1][(nt & 1) * 2]);
        }

        if (j0 < SEQ_N) {
#pragma unroll
            for (int nt = 0; nt < 8; nt++) {
                const int gk = j0 + nt * 8 + 2 * tg;
                if (gk > gq0)     s[nt][0] = MASK_VAL;
                if (gk + 1 > gq0) s[nt][1] = MASK_VAL;
                if (gk > gq1)     s[nt][2] = MASK_VAL;
                if (gk + 1 > gq1) s[nt][3] = MASK_VAL;
            }
        }

        float mx0 = -1e30f, mx1 = -1e30f;
#pragma unroll
        for (int nt = 0; nt < 8; nt++) {
            mx0 = fmaxf(mx0, fmaxf(s[nt][0], s[nt][1]));
            mx1 = fmaxf(mx1, fmaxf(s[nt][2], s[nt][3]));
        }
        mx0 = fmaxf(mx0, __shfl_xor_sync(0xffffffffu, mx0, 1));
        mx0 = fmaxf(mx0, __shfl_xor_sync(0xffffffffu, mx0, 2));
        mx1 = fmaxf(mx1, __shfl_xor_sync(0xffffffffu, mx1, 1));
        mx1 = fmaxf(mx1, __shfl_xor_sync(0xffffffffu, mx1, 2));
        const float mn0 = fmaxf(m0, mx0);
        const float mn1 = fmaxf(m1, mx1);
        const float fac0 = exp2f(m0 - mn0);
        const float fac1 = exp2f(m1 - mn1);
        float sum0 = 0.0f, sum1 = 0.0f;
#pragma unroll
        for (int nt = 0; nt < 8; nt++) {
            s[nt][0] = exp2f(s[nt][0] - mn0);
            s[nt][1] = exp2f(s[nt][1] - mn0);
            s[nt][2] = exp2f(s[nt][2] - mn1);
            s[nt][3] = exp2f(s[nt][3] - mn1);
            sum0 += s[nt][0] + s[nt][1];
            sum1 += s[nt][2] + s[nt][3];
        }
        sum0 += __shfl_xor_sync(0xffffffffu, sum0, 1);
        sum0 += __shfl_xor_sync(0xffffffffu, sum0, 2);
        sum1 += __shfl_xor_sync(0xffffffffu, sum1, 1);
        sum1 += __shfl_xor_sync(0xffffffffu, sum1, 2);
        l0 = l0 * fac0 + sum0;
        l1 = l1 * fac1 + sum1;
        m0 = mn0; m1 = mn1;
#pragma unroll
        for (int nt = 0; nt < 8; nt++) {
            accO[nt][0] *= fac0; accO[nt][1] *= fac0;
            accO[nt][2] *= fac1; accO[nt][3] *= fac1;
        }
        __half* Ps = smh + AQ_PS;
#pragma unroll
        for (int nt = 0; nt < 8; nt++) {
            *reinterpret_cast<uint32_t*>(&Ps[(wq0 + g) * HS + nt * 8 + 2 * tg]) =
                pk2(s[nt][0], s[nt][1]);
            *reinterpret_cast<uint32_t*>(&Ps[(wq0 + g + 8) * HS + nt * 8 + 2 * tg]) =
                pk2(s[nt][2], s[nt][3]);
        }
        __syncwarp();

#pragma unroll
        for (int kf = 0; kf < 4; kf++) {
            const int kk = kf * 16;
            uint32_t a[4];
            ldsm4(a, uPs + (wq0 + arow) * (HS * 2) + (kk + acol) * 2);
            uint32_t bf[4][4];
#pragma unroll
            for (int p = 0; p < 4; p++)
                ldsm4t(bf[p], uVs + (kk + vkrow) * (HS * 2) + (p * 16 + vncol) * 2);
#pragma unroll
            for (int nt = 0; nt < 8; nt++)
                mma16(accO[nt], a, &bf[nt >> 1][(nt & 1) * 2]);
        }
        stage ^= 1;
        j0 = nj;
    }

    const float inv0 = 1.0f / l0;
    const float inv1 = 1.0f / l1;
#pragma unroll
    for (int nt = 0; nt < 8; nt++) {
        const int col = h * DH + nt * 8 + 2 * tg;
        *reinterpret_cast<uint32_t*>(Oh + (size_t)gq0 * DIM + col) =
            pk2(accO[nt][0] * inv0, accO[nt][1] * inv0);
        *reinterpret_cast<uint32_t*>(Oh + (size_t)gq1 * DIM + col) =
            pk2(accO[nt][2] * inv1, accO[nt][3] * inv1);
    }
}

// ---------------------------------------------------------------------------
// LayerNorm (vectorized)
// ---------------------------------------------------------------------------
template <bool WH>
__global__ void __launch_bounds__(256)
ln_kernel(const float* __restrict__ a, const float* __restrict__ g,
          const float* __restrict__ beta, float* __restrict__ out,
          __half* __restrict__ outh)
{
    const int row = blockIdx.x;
    const int c0 = threadIdx.x * 4;
    __shared__ float sh1[8], sh2[8];

    const float4 v = *reinterpret_cast<const float4*>(a + (size_t)row * DIM + c0);
    float s = v.x + v.y + v.z + v.w;
#pragma unroll
    for (int off = 16; off >= 1; off >>= 1) s += __shfl_xor_sync(0xffffffffu, s, off);
    if ((threadIdx.x & 31) == 0) sh1[threadIdx.x >> 5] = s;
    __syncthreads();
    float mu = 0.0f;
#pragma unroll
    for (int i = 0; i < 8; i++) mu += sh1[i];
    mu *= (1.0f / DIM);

    float d0 = v.x - mu, d1 = v.y - mu, d2 = v.z - mu, d3 = v.w - mu;
    float vs = d0 * d0 + d1 * d1 + d2 * d2 + d3 * d3;
#pragma unroll
    for (int off = 16; off >= 1; off >>= 1) vs += __shfl_xor_sync(0xffffffffu, vs, off);
    if ((threadIdx.x & 31) == 0) sh2[threadIdx.x >> 5] = vs;
    __syncthreads();
    float var = 0.0f;
#pragma unroll
    for (int i = 0; i < 8; i++) var += sh2[i];
    const float inv = rsqrtf(var * (1.0f / DIM) + 1e-5f);

    const float4 gv = *reinterpret_cast<const float4*>(g + c0);
    const float4 bv = *reinterpret_cast<const float4*>(beta + c0);
    float4 o;
    o.x = d0 * inv * gv.x + bv.x;
    o.y = d1 * inv * gv.y + bv.y;
    o.z = d2 * inv * gv.z + bv.z;
    o.w = d3 * inv * gv.w + bv.w;
    *reinterpret_cast<float4*>(out + (size_t)row * DIM + c0) = o;
    if (WH) {
        uint2 ho; ho.x = pk2(o.x, o.y); ho.y = pk2(o.z, o.w);
        *reinterpret_cast<uint2*>(outh + (size_t)row * DIM + c0) = ho;
    }
}

// ---------------------------------------------------------------------------
// Launch (R11 structure: single-stream chain, weight-prep fork on s2)
// ---------------------------------------------------------------------------
extern "C" void kernel_launch(void* const* d_in, const int* in_sizes, int n_in,
                              void* d_out, int out_size)
{
    const float* x     = (const float*)d_in[0];
    const float* ctx   = (const float*)d_in[1];
    const float* Wq    = (const float*)d_in[2];
    const float* bq    = (const float*)d_in[3];
    const float* Wkv   = (const float*)d_in[4];
    const float* bkv   = (const float*)d_in[5];
    const float* Wo    = (const float*)d_in[6];
    const float* bo    = (const float*)d_in[7];
    const float* ln1g  = (const float*)d_in[8];
    const float* ln1b  = (const float*)d_in[9];
    const float* W1    = (const float*)d_in[10];
    const float* bf1   = (const float*)d_in[11];
    const float* W2    = (const float*)d_in[12];
    const float* bf2   = (const float*)d_in[13];
    const float* ln2g  = (const float*)d_in[14];
    const float* ln2b  = (const float*)d_in[15];
    float* out = (float*)d_out;

    __half *inh, *qh, *kvh, *attnh, *x1h, *ffh, *wqT, *wkvT, *woT, *w1T, *w2T;
    float *t, *x1;
    cudaGetSymbolAddress((void**)&inh,   g_inh);
    cudaGetSymbolAddress((void**)&qh,    g_qh);
    cudaGetSymbolAddress((void**)&kvh,   g_kvh);
    cudaGetSymbolAddress((void**)&attnh, g_attnh);
    cudaGetSymbolAddress((void**)&x1h,   g_x1h);
    cudaGetSymbolAddress((void**)&ffh,   g_ffh);
    cudaGetSymbolAddress((void**)&t,     g_t);
    cudaGetSymbolAddress((void**)&x1,    g_x1);
    cudaGetSymbolAddress((void**)&wqT,   g_wqT);
    cudaGetSymbolAddress((void**)&wkvT,  g_wkvT);
    cudaGetSymbolAddress((void**)&woT,   g_woT);
    cudaGetSymbolAddress((void**)&w1T,   g_w1T);
    cudaGetSymbolAddress((void**)&w2T,   g_w2T);

    cudaFuncSetAttribute(attn_kernel, cudaFuncAttributeMaxDynamicSharedMemorySize, ATT_SMEM);
    cudaFuncSetAttribute(qkv_gemm,    cudaFuncAttributeMaxDynamicSharedMemorySize, GEMM_SMEM);
    cudaFuncSetAttribute(mma_gemm<2>, cudaFuncAttributeMaxDynamicSharedMemorySize, GEMM_SMEM);
    cudaFuncSetAttribute(mma_gemm<3>, cudaFuncAttributeMaxDynamicSharedMemorySize, GEMM_SMEM);

    static cudaStream_t s2 = nullptr;
    static cudaEvent_t eBegin = nullptr, eQKVw = nullptr, eW = nullptr;
    if (s2 == nullptr) {
        cudaStreamCreateWithFlags(&s2, cudaStreamNonBlocking);
        cudaEventCreateWithFlags(&eBegin, cudaEventDisableTiming);
        cudaEventCreateWithFlags(&eQKVw,  cudaEventDisableTiming);
        cudaEventCreateWithFlags(&eW,     cudaEventDisableTiming);
    }

    // ---- fork: weight transposes on s2 ----
    cudaEventRecord(eBegin, 0);
    cudaStreamWaitEvent(s2, eBegin, 0);
    transpose_h_kernel<<<dim3(DIM / 32, DIM / 32), 256, 0, s2>>>(Wq,  wqT,  DIM,  DIM);
    transpose_h_kernel<<<dim3(2 * DIM / 32, DIM / 32), 256, 0, s2>>>(Wkv, wkvT, DIM, 2 * DIM);
    cudaEventRecord(eQKVw, s2);
    transpose_h_kernel<<<dim3(DIM / 32, DIM / 32), 256, 0, s2>>>(Wo,  woT,  DIM,  DIM);
    transpose_h_kernel<<<dim3(DFF_ / 32, DIM / 32), 256, 0, s2>>>(W1,  w1T,  DIM,  DFF_);
    transpose_h_kernel<<<dim3(DIM / 32, DFF_ / 32), 256, 0, s2>>>(W2,  w2T,  DFF_, DIM);
    cudaEventRecord(eW, s2);

    // main: activation convert
    convert_h_kernel<<<TOTK * DIM / (256 * 8), 256>>>(x, ctx, inh);

    // 1+2) merged QKV projection (Q gets alpha = log2e/8)
    cudaStreamWaitEvent(0, eQKVw, 0);
    qkv_gemm<<<640, 128, GEMM_SMEM>>>(inh, wqT, wkvT, bq, bkv, qh, kvh,
                                      0.18033688011112042f);

    // 3) attention -> attnh
    attn_kernel<<<dim3(SEQ_N / QROWS, HEADS), 512, ATT_SMEM>>>(qh, kvh, attnh);

    // ---- join: remaining weights ready ----
    cudaStreamWaitEvent(0, eW, 0);

    // 4) t = attn @ Wo + bo + x
    mma_gemm<3><<<dim3(DIM / 128, SEQ_N / 128), 128, GEMM_SMEM>>>(
        attnh, woT, bo, x, t, nullptr, DIM, DIM);

    // 5) x1 = LN1(t)
    ln_kernel<true><<<SEQ_N, 256>>>(t, ln1g, ln1b, x1, x1h);

    // 6) ffh = gelu(x1 @ W1 + bf1)
    mma_gemm<2><<<dim3(DFF_ / 128, SEQ_N / 128), 128, GEMM_SMEM>>>(
        x1h, w1T, bf1, nullptr, nullptr, ffh, DFF_, DIM);

    // 7) t = ff @ W2 + bf2 + x1
    mma_gemm<3><<<dim3(DIM / 128, SEQ_N / 128), 128, GEMM_SMEM>>>(
        ffh, w2T, bf2, x1, t, nullptr, DIM, DFF_);

    // 8) out = LN2(t)
    ln_kernel<false><<<SEQ_N, 256>>>(t, ln2g, ln2b, out, nullptr);
}

// round 16
// speedup vs baseline: 1.0373x; 1.0140x over previous
#include <cuda_runtime.h>
#include <cuda_fp16.h>
#include <math.h>
#include <stdint.h>

// R16 = exact R11 configuration (best measured: 483.4us).
// Post-R15 conclusion: composite HMMA-wall plateau reached; 4-stage pipeline
// (R15) regressed via occupancy 3->2 CTAs/SM and is reverted. This locks the
// best-known kernel: 3-stage cp.async GEMM (61.4KB smem, 3 CTAs/SM), merged
// QKV projection, QROWS=256 attention with double-buffered K/V, weight
// transposes forked on a second stream.

// ---------------------------------------------------------------------------
// Problem constants
// ---------------------------------------------------------------------------
#define SEQ_N 2048
#define SEQ_M 2048
#define TOTK  (SEQ_N + SEQ_M)   // 4096
#define DIM   1024
#define HEADS 16
#define DH    64
#define DFF_  4096
#define MASK_VAL (-50000.0f)

// ---------------------------------------------------------------------------
// Scratch (device globals; no allocation allowed)
// ---------------------------------------------------------------------------
__device__ __half g_inh [TOTK * DIM];
__device__ __half g_qh  [SEQ_N * DIM];
__device__ __half g_kvh [TOTK * 2 * DIM];
__device__ __half g_attnh[SEQ_N * DIM];
__device__ __half g_x1h [SEQ_N * DIM];
__device__ __half g_ffh [SEQ_N * DFF_];
__device__ float  g_t   [SEQ_N * DIM];
__device__ float  g_x1  [SEQ_N * DIM];
__device__ __half g_wqT [DIM * DIM];
__device__ __half g_wkvT[2 * DIM * DIM];
__device__ __half g_woT [DIM * DIM];
__device__ __half g_w1T [DFF_ * DIM];
__device__ __half g_w2T [DIM * DFF_];

// ---------------------------------------------------------------------------
// Helpers
// ---------------------------------------------------------------------------
__device__ __forceinline__ uint32_t pk2(float a, float b) {
    __half2 h = __floats2half2_rn(a, b);
    return *reinterpret_cast<uint32_t*>(&h);
}
__device__ __forceinline__ void mma16(float* c, const uint32_t* a, const uint32_t* b) {
    asm volatile(
        "mma.sync.aligned.m16n8k16.row.col.f32.f16.f16.f32 "
        "{%0,%1,%2,%3}, {%4,%5,%6,%7}, {%8,%9}, {%0,%1,%2,%3};"
        : "+f"(c[0]), "+f"(c[1]), "+f"(c[2]), "+f"(c[3])
        : "r"(a[0]), "r"(a[1]), "r"(a[2]), "r"(a[3]), "r"(b[0]), "r"(b[1]));
}
__device__ __forceinline__ void ldsm4(uint32_t* r, uint32_t addr) {
    asm volatile("ldmatrix.sync.aligned.m8n8.x4.shared.b16 {%0,%1,%2,%3}, [%4];"
                 : "=r"(r[0]), "=r"(r[1]), "=r"(r[2]), "=r"(r[3]) : "r"(addr));
}
__device__ __forceinline__ void ldsm4t(uint32_t* r, uint32_t addr) {
    asm volatile("ldmatrix.sync.aligned.m8n8.x4.trans.shared.b16 {%0,%1,%2,%3}, [%4];"
                 : "=r"(r[0]), "=r"(r[1]), "=r"(r[2]), "=r"(r[3]) : "r"(addr));
}
__device__ __forceinline__ void cp16(uint32_t saddr, const void* g) {
    asm volatile("cp.async.cg.shared.global [%0], [%1], 16;" :: "r"(saddr), "l"(g));
}
__device__ __forceinline__ void cp_commit() {
    asm volatile("cp.async.commit_group;" ::: "memory");
}
template <int NN>
__device__ __forceinline__ void cp_wait() {
    asm volatile("cp.async.wait_group %0;" :: "n"(NN) : "memory");
}

// ---------------------------------------------------------------------------
// convert concat(x, ctx) -> fp16 g_inh
// ---------------------------------------------------------------------------
__global__ void __launch_bounds__(256)
convert_h_kernel(const float* __restrict__ x, const float* __restrict__ ctx,
                 __half* __restrict__ out)
{
    const size_t i = ((size_t)blockIdx.x * 256 + threadIdx.x) * 8;
    const float* src = (i < (size_t)SEQ_N * DIM) ? x + i
                                                 : ctx + (i - (size_t)SEQ_N * DIM);
    const float4 a = *reinterpret_cast<const float4*>(src);
    const float4 b = *reinterpret_cast<const float4*>(src + 4);
    uint4 o;
    o.x = pk2(a.x, a.y); o.y = pk2(a.z, a.w);
    o.z = pk2(b.x, b.y); o.w = pk2(b.z, b.w);
    *reinterpret_cast<uint4*>(out + i) = o;
}

// ---------------------------------------------------------------------------
// Weight transpose + fp16
// ---------------------------------------------------------------------------
__global__ void __launch_bounds__(256)
transpose_h_kernel(const float* __restrict__ in, __half* __restrict__ out, int K, int N)
{
    __shared__ float t[32][33];
    const int bx = blockIdx.x * 32;
    const int by = blockIdx.y * 32;
    const int x = threadIdx.x & 31;
    const int y = threadIdx.x >> 5;
#pragma unroll
    for (int i = 0; i < 32; i += 8)
        t[y + i][x] = in[(size_t)(by + y + i) * N + bx + x];
    __syncthreads();
#pragma unroll
    for (int i = 0; i < 32; i += 8)
        out[(size_t)(bx + y + i) * K + by + x] = __float2half_rn(t[x][y + i]);
}

// ---------------------------------------------------------------------------
// GEMM core (tile 128x128, K-chunk 32, 128 threads, cp.async 3 stage)
// ---------------------------------------------------------------------------
#define ABYTES 10240
#define STAGE_B (2 * ABYTES)
#define GEMM_SMEM (3 * STAGE_B)   // 61440 B -> 3 CTAs/SM

struct GemmCtx {
    uint32_t smemU;
    int lane, g, tg, warp_m, warp_n, crow, cq;
    int arow, acol, brow, bcol;
};
__device__ __forceinline__ GemmCtx gemm_ctx(uint32_t smemU) {
    GemmCtx c;
    const int tid = threadIdx.x;
    c.smemU = smemU;
    c.lane = tid & 31;
    const int wid = tid >> 5;
    c.g = c.lane >> 2; c.tg = c.lane & 3;
    c.warp_m = wid >> 1; c.warp_n = wid & 1;
    c.crow = tid >> 2; c.cq = tid & 3;
    c.arow = c.lane & 15;
    c.acol = (c.lane >> 4) * 8;
    c.brow = (c.lane & 7) + ((c.lane >> 4) & 1) * 8;
    c.bcol = ((c.lane >> 3) & 1) * 8;
    return c;
}

__device__ __forceinline__ void gemm_issue(const GemmCtx& c, const __half* Ah,
                                           const __half* Bt, int tileM, int tileN,
                                           int K, int chunk, int stage) {
    const uint32_t base = c.smemU + stage * STAGE_B;
    const size_t koff = (size_t)chunk * 32 + c.cq * 8;
#pragma unroll
    for (int rr = 0; rr < 4; rr++) {
        const int row = c.crow + rr * 32;
        cp16(base + row * 80 + c.cq * 16, Ah + (size_t)(tileM + row) * K + koff);
        cp16(base + ABYTES + row * 80 + c.cq * 16, Bt + (size_t)(tileN + row) * K + koff);
    }
    cp_commit();
}

__device__ __forceinline__ void gemm_consume(const GemmCtx& c, int stage,
                                             float acc[4][8][4]) {
    const uint32_t aBase = c.smemU + stage * STAGE_B;
    const uint32_t bBase = aBase + ABYTES;
#pragma unroll
    for (int kk = 0; kk < 32; kk += 16) {
        uint32_t af[4][4];
        uint32_t bf[4][4];
#pragma unroll
        for (int mt = 0; mt < 4; mt++)
            ldsm4(af[mt], aBase + (c.warp_m * 64 + mt * 16 + c.arow) * 80
                          + (kk + c.acol) * 2);
#pragma unroll
        for (int p = 0; p < 4; p++)
            ldsm4(bf[p], bBase + (c.warp_n * 64 + p * 16 + c.brow) * 80
                         + (kk + c.bcol) * 2);
#pragma unroll
        for (int mt = 0; mt < 4; mt++)
#pragma unroll
            for (int nt = 0; nt < 8; nt++)
                mma16(acc[mt][nt], af[mt], &bf[nt >> 1][(nt & 1) * 2]);
    }
}

__device__ __forceinline__ void gemm_main(const GemmCtx& c, const __half* Ah,
                                          const __half* Bt, int tileM, int tileN,
                                          int K, float acc[4][8][4]) {
#pragma unroll
    for (int i = 0; i < 4; i++)
#pragma unroll
        for (int j = 0; j < 8; j++)
#pragma unroll
            for (int l = 0; l < 4; l++) acc[i][j][l] = 0.0f;

    const int NKC = K / 32;
    gemm_issue(c, Ah, Bt, tileM, tileN, K, 0, 0);
    if (NKC > 1) gemm_issue(c, Ah, Bt, tileM, tileN, K, 1, 1);

    for (int kc = 0; kc < NKC; kc++) {
        const int s = kc % 3;
        if (kc < NKC - 1) cp_wait<1>(); else cp_wait<0>();
        __syncthreads();
        if (kc + 2 < NKC) gemm_issue(c, Ah, Bt, tileM, tileN, K, kc + 2, (kc + 2) % 3);
        gemm_consume(c, s, acc);
    }
}

// ---------------------------------------------------------------------------
// Merged QKV projection: 640 tiles. idx<512 -> KV [4096,2048]; else Q.
// ---------------------------------------------------------------------------
__global__ void __launch_bounds__(128)
qkv_gemm(const __half* __restrict__ Ah,
         const __half* __restrict__ wqT, const __half* __restrict__ wkvT,
         const float* __restrict__ bq, const float* __restrict__ bkv,
         __half* __restrict__ qh, __half* __restrict__ kvh, float alphaQ)
{
    extern __shared__ __half smem_h[];
    GemmCtx c = gemm_ctx((uint32_t)__cvta_generic_to_shared(smem_h));

    const int idx = blockIdx.x;
    int tileM, tileN, N;
    const __half* Bt;
    const float* bias;
    __half* Ch;
    float alpha;
    if (idx < 512) {
        tileM = (idx >> 4) * 128; tileN = (idx & 15) * 128;
        N = 2 * DIM; Bt = wkvT; bias = bkv; Ch = kvh; alpha = 1.0f;
    } else {
        const int q = idx - 512;
        tileM = (q >> 3) * 128; tileN = (q & 7) * 128;
        N = DIM; Bt = wqT; bias = bq; Ch = qh; alpha = alphaQ;
    }

    float acc[4][8][4];
    gemm_main(c, Ah, Bt, tileM, tileN, DIM, acc);

#pragma unroll
    for (int mt = 0; mt < 4; mt++) {
        const int r0 = tileM + c.warp_m * 64 + mt * 16 + c.g;
#pragma unroll
        for (int nt = 0; nt < 8; nt++) {
            const int col = tileN + c.warp_n * 64 + nt * 8 + c.tg * 2;
            const float2 bv = *reinterpret_cast<const float2*>(bias + col);
#pragma unroll
            for (int hh = 0; hh < 2; hh++) {
                const int r = r0 + hh * 8;
                const float v0 = (acc[mt][nt][hh * 2 + 0] + bv.x) * alpha;
                const float v1 = (acc[mt][nt][hh * 2 + 1] + bv.y) * alpha;
                *reinterpret_cast<uint32_t*>(Ch + (size_t)r * N + col) = pk2(v0, v1);
            }
        }
    }
}

// ---------------------------------------------------------------------------
// General GEMM: EPI 2: half gelu(acc+bias); EPI 3: float acc+bias+resid
// ---------------------------------------------------------------------------
template <int EPI>
__global__ void __launch_bounds__(128)
mma_gemm(const __half* __restrict__ Ah, const __half* __restrict__ Bt,
         const float* __restrict__ bias, const float* __restrict__ resid,
         float* __restrict__ Cf, __half* __restrict__ Ch,
         int N, int K)
{
    extern __shared__ __half smem_h[];
    GemmCtx c = gemm_ctx((uint32_t)__cvta_generic_to_shared(smem_h));

    const int tileM = blockIdx.y * 128;
    const int tileN = blockIdx.x * 128;

    float acc[4][8][4];
    gemm_main(c, Ah, Bt, tileM, tileN, K, acc);

#pragma unroll
    for (int mt = 0; mt < 4; mt++) {
        const int r0 = tileM + c.warp_m * 64 + mt * 16 + c.g;
#pragma unroll
        for (int nt = 0; nt < 8; nt++) {
            const int col = tileN + c.warp_n * 64 + nt * 8 + c.tg * 2;
            const float2 bv = *reinterpret_cast<const float2*>(bias + col);
#pragma unroll
            for (int hh = 0; hh < 2; hh++) {
                const int r = r0 + hh * 8;
                float v0 = acc[mt][nt][hh * 2 + 0] + bv.x;
                float v1 = acc[mt][nt][hh * 2 + 1] + bv.y;
                if (EPI == 2) {
                    v0 = 0.5f * v0 * (1.0f + erff(v0 * 0.70710678118654752f));
                    v1 = 0.5f * v1 * (1.0f + erff(v1 * 0.70710678118654752f));
                    *reinterpret_cast<uint32_t*>(Ch + (size_t)r * N + col) = pk2(v0, v1);
                } else {
                    const float2 rv = *reinterpret_cast<const float2*>(
                        resid + (size_t)r * N + col);
                    float2 o; o.x = v0 + rv.x; o.y = v1 + rv.y;
                    *reinterpret_cast<float2*>(Cf + (size_t)r * N + col) = o;
                }
            }
        }
    }
}

// ---------------------------------------------------------------------------
// Flash attention: QROWS=256, 512 threads, cp.async double-buffered K/V,
// V via ldmatrix.trans, exp2-domain softmax (log2e folded into Q).
// ---------------------------------------------------------------------------
#define QROWS 256
#define HS 72
#define AQ_QS 0
#define AQ_K0 (QROWS * HS)               // 18432
#define AQ_PS (AQ_K0 + 4 * 64 * HS)      // 36864
#define AQ_HALFS (AQ_PS + QROWS * HS)    // 55296
#define ATT_SMEM (AQ_HALFS * 2)          // 110592 B

__global__ void __launch_bounds__(512)
attn_kernel(const __half* __restrict__ Qh,
            const __half* __restrict__ KVh,
            __half* __restrict__ Oh)
{
    extern __shared__ __half smh[];
    const uint32_t uBase = (uint32_t)__cvta_generic_to_shared(smh);
    const uint32_t uQs = uBase;
    const uint32_t uPs = uBase + AQ_PS * 2;

    const int h   = blockIdx.y;
    const int q0  = blockIdx.x * QROWS;
    const int tid = threadIdx.x;
    const int wid = tid >> 5;
    const int lane = tid & 31;
    const int g   = lane >> 2;
    const int tg  = lane & 3;
    const int wq0 = wid * 16;

    __half* Qs = smh + AQ_QS;
    for (int e = tid; e < QROWS * 8; e += 512) {
        const int row = e >> 3, cc = e & 7;
        *reinterpret_cast<uint4*>(&Qs[row * HS + cc * 8]) =
            *reinterpret_cast<const uint4*>(Qh + (size_t)(q0 + row) * DIM + h * DH + cc * 8);
    }

    float m0 = -1e30f, m1 = -1e30f, l0 = 0.0f, l1 = 0.0f;
    float accO[8][4];
#pragma unroll
    for (int nt = 0; nt < 8; nt++)
#pragma unroll
        for (int i = 0; i < 4; i++) accO[nt][i] = 0.0f;

    const int prow = tid >> 3, pcc = tid & 7;
    auto issue_kv = [&](int j, int s) {
        const uint32_t uK = uBase + (AQ_K0 + s * 2 * 64 * HS) * 2;
        const uint32_t uV = uK + 64 * HS * 2;
        const __half* src = KVh + (size_t)(j + prow) * (2 * DIM) + h * DH + pcc * 8;
        cp16(uK + prow * (HS * 2) + pcc * 16, src);
        cp16(uV + prow * (HS * 2) + pcc * 16, src + DIM);
        cp_commit();
    };

    const int gq0 = q0 + wq0 + g;
    const int gq1 = gq0 + 8;

    const int arow = lane & 15;
    const int acol = (lane >> 4) * 8;
    const int brow = (lane & 7) + ((lane >> 4) & 1) * 8;
    const int bcol = ((lane >> 3) & 1) * 8;
    const int vkrow = (lane & 7) + ((lane >> 3) & 1) * 8;
    const int vncol = ((lane >> 4) & 1) * 8;

    int j0 = 0;
    int stage = 0;
    issue_kv(0, 0);
    while (j0 < TOTK) {
        int nj = j0 + 64;
        if (nj >= q0 + QROWS && nj < SEQ_N) nj = SEQ_N;  // causal tile skip

        __syncthreads();
        if (nj < TOTK) {
            issue_kv(nj, stage ^ 1);
            cp_wait<1>();
        } else {
            cp_wait<0>();
        }
        __syncthreads();

        const uint32_t uKs = uBase + (AQ_K0 + stage * 2 * 64 * HS) * 2;
        const uint32_t uVs = uKs + 64 * HS * 2;

        float s[8][4];
#pragma unroll
        for (int nt = 0; nt < 8; nt++)
#pragma unroll
            for (int i = 0; i < 4; i++) s[nt][i] = 0.0f;
#pragma unroll
        for (int kf = 0; kf < 4; kf++) {
            const int kk = kf * 16;
            uint32_t a[4];
            ldsm4(a, uQs + (wq0 + arow) * (HS * 2) + (kk + acol) * 2);
            uint32_t bf[4][4];
#pragma unroll
            for (int p = 0; p < 4; p++)
                ldsm4(bf[p], uKs + (p * 16 + brow) * (HS * 2) + (kk + bcol) * 2);
#pragma unroll
            for (int nt = 0; nt < 8; nt++)
                mma16(s[nt], a, &bf[nt >> 1][(nt & 1) * 2]);
        }

        if (j0 < SEQ_N) {
#pragma unroll
            for (int nt = 0; nt < 8; nt++) {
                const int gk = j0 + nt * 8 + 2 * tg;
                if (gk > gq0)     s[nt][0] = MASK_VAL;
                if (gk + 1 > gq0) s[nt][1] = MASK_VAL;
                if (gk > gq1)     s[nt][2] = MASK_VAL;
                if (gk + 1 > gq1) s[nt][3] = MASK_VAL;
            }
        }

        float mx0 = -1e30f, mx1 = -1e30f;
#pragma unroll
        for (int nt = 0; nt < 8; nt++) {
            mx0 = fmaxf(mx0, fmaxf(s[nt][0], s[nt][1]));
            mx1 = fmaxf(mx1, fmaxf(s[nt][2], s[nt][3]));
        }
        mx0 = fmaxf(mx0, __shfl_xor_sync(0xffffffffu, mx0, 1));
        mx0 = fmaxf(mx0, __shfl_xor_sync(0xffffffffu, mx0, 2));
        mx1 = fmaxf(mx1, __shfl_xor_sync(0xffffffffu, mx1, 1));
        mx1 = fmaxf(mx1, __shfl_xor_sync(0xffffffffu, mx1, 2));
        const float mn0 = fmaxf(m0, mx0);
        const float mn1 = fmaxf(m1, mx1);
        const float fac0 = exp2f(m0 - mn0);
        const float fac1 = exp2f(m1 - mn1);
        float sum0 = 0.0f, sum1 = 0.0f;
#pragma unroll
        for (int nt = 0; nt < 8; nt++) {
            s[nt][0] = exp2f(s[nt][0] - mn0);
            s[nt][1] = exp2f(s[nt][1] - mn0);
            s[nt][2] = exp2f(s[nt][2] - mn1);
            s[nt][3] = exp2f(s[nt][3] - mn1);
            sum0 += s[nt][0] + s[nt][1];
            sum1 += s[nt][2] + s[nt][3];
        }
        sum0 += __shfl_xor_sync(0xffffffffu, sum0, 1);
        sum0 += __shfl_xor_sync(0xffffffffu, sum0, 2);
        sum1 += __shfl_xor_sync(0xffffffffu, sum1, 1);
        sum1 += __shfl_xor_sync(0xffffffffu, sum1, 2);
        l0 = l0 * fac0 + sum0;
        l1 = l1 * fac1 + sum1;
        m0 = mn0; m1 = mn1;
#pragma unroll
        for (int nt = 0; nt < 8; nt++) {
            accO[nt][0] *= fac0; accO[nt][1] *= fac0;
            accO[nt][2] *= fac1; accO[nt][3] *= fac1;
        }
        __half* Ps = smh + AQ_PS;
#pragma unroll
        for (int nt = 0; nt < 8; nt++) {
            *reinterpret_cast<uint32_t*>(&Ps[(wq0 + g) * HS + nt * 8 + 2 * tg]) =
                pk2(s[nt][0], s[nt][1]);
            *reinterpret_cast<uint32_t*>(&Ps[(wq0 + g + 8) * HS + nt * 8 + 2 * tg]) =
                pk2(s[nt][2], s[nt][3]);
        }
        __syncwarp();

#pragma unroll
        for (int kf = 0; kf < 4; kf++) {
            const int kk = kf * 16;
            uint32_t a[4];
            ldsm4(a, uPs + (wq0 + arow) * (HS * 2) + (kk + acol) * 2);
            uint32_t bf[4][4];
#pragma unroll
            for (int p = 0; p < 4; p++)
                ldsm4t(bf[p], uVs + (kk + vkrow) * (HS * 2) + (p * 16 + vncol) * 2);
#pragma unroll
            for (int nt = 0; nt < 8; nt++)
                mma16(accO[nt], a, &bf[nt >> 1][(nt & 1) * 2]);
        }
        stage ^= 1;
        j0 = nj;
    }

    const float inv0 = 1.0f / l0;
    const float inv1 = 1.0f / l1;
#pragma unroll
    for (int nt = 0; nt < 8; nt++) {
        const int col = h * DH + nt * 8 + 2 * tg;
        *reinterpret_cast<uint32_t*>(Oh + (size_t)gq0 * DIM + col) =
            pk2(accO[nt][0] * inv0, accO[nt][1] * inv0);
        *reinterpret_cast<uint32_t*>(Oh + (size_t)gq1 * DIM + col) =
            pk2(accO[nt][2] * inv1, accO[nt][3] * inv1);
    }
}

// ---------------------------------------------------------------------------
// LayerNorm (vectorized)
// ---------------------------------------------------------------------------
template <bool WH>
__global__ void __launch_bounds__(256)
ln_kernel(const float* __restrict__ a, const float* __restrict__ g,
          const float* __restrict__ beta, float* __restrict__ out,
          __half* __restrict__ outh)
{
    const int row = blockIdx.x;
    const int c0 = threadIdx.x * 4;
    __shared__ float sh1[8], sh2[8];

    const float4 v = *reinterpret_cast<const float4*>(a + (size_t)row * DIM + c0);
    float s = v.x + v.y + v.z + v.w;
#pragma unroll
    for (int off = 16; off >= 1; off >>= 1) s += __shfl_xor_sync(0xffffffffu, s, off);
    if ((threadIdx.x & 31) == 0) sh1[threadIdx.x >> 5] = s;
    __syncthreads();
    float mu = 0.0f;
#pragma unroll
    for (int i = 0; i < 8; i++) mu += sh1[i];
    mu *= (1.0f / DIM);

    float d0 = v.x - mu, d1 = v.y - mu, d2 = v.z - mu, d3 = v.w - mu;
    float vs = d0 * d0 + d1 * d1 + d2 * d2 + d3 * d3;
#pragma unroll
    for (int off = 16; off >= 1; off >>= 1) vs += __shfl_xor_sync(0xffffffffu, vs, off);
    if ((threadIdx.x & 31) == 0) sh2[threadIdx.x >> 5] = vs;
    __syncthreads();
    float var = 0.0f;
#pragma unroll
    for (int i = 0; i < 8; i++) var += sh2[i];
    const float inv = rsqrtf(var * (1.0f / DIM) + 1e-5f);

    const float4 gv = *reinterpret_cast<const float4*>(g + c0);
    const float4 bv = *reinterpret_cast<const float4*>(beta + c0);
    float4 o;
    o.x = d0 * inv * gv.x + bv.x;
    o.y = d1 * inv * gv.y + bv.y;
    o.z = d2 * inv * gv.z + bv.z;
    o.w = d3 * inv * gv.w + bv.w;
    *reinterpret_cast<float4*>(out + (size_t)row * DIM + c0) = o;
    if (WH) {
        uint2 ho; ho.x = pk2(o.x, o.y); ho.y = pk2(o.z, o.w);
        *reinterpret_cast<uint2*>(outh + (size_t)row * DIM + c0) = ho;
    }
}

// ---------------------------------------------------------------------------
// Launch (single-stream chain, weight-prep fork on s2)
// ---------------------------------------------------------------------------
extern "C" void kernel_launch(void* const* d_in, const int* in_sizes, int n_in,
                              void* d_out, int out_size)
{
    const float* x     = (const float*)d_in[0];
    const float* ctx   = (const float*)d_in[1];
    const float* Wq    = (const float*)d_in[2];
    const float* bq    = (const float*)d_in[3];
    const float* Wkv   = (const float*)d_in[4];
    const float* bkv   = (const float*)d_in[5];
    const float* Wo    = (const float*)d_in[6];
    const float* bo    = (const float*)d_in[7];
    const float* ln1g  = (const float*)d_in[8];
    const float* ln1b  = (const float*)d_in[9];
    const float* W1    = (const float*)d_in[10];
    const float* bf1   = (const float*)d_in[11];
    const float* W2    = (const float*)d_in[12];
    const float* bf2   = (const float*)d_in[13];
    const float* ln2g  = (const float*)d_in[14];
    const float* ln2b  = (const float*)d_in[15];
    float* out = (float*)d_out;

    __half *inh, *qh, *kvh, *attnh, *x1h, *ffh, *wqT, *wkvT, *woT, *w1T, *w2T;
    float *t, *x1;
    cudaGetSymbolAddress((void**)&inh,   g_inh);
    cudaGetSymbolAddress((void**)&qh,    g_qh);
    cudaGetSymbolAddress((void**)&kvh,   g_kvh);
    cudaGetSymbolAddress((void**)&attnh, g_attnh);
    cudaGetSymbolAddress((void**)&x1h,   g_x1h);
    cudaGetSymbolAddress((void**)&ffh,   g_ffh);
    cudaGetSymbolAddress((void**)&t,     g_t);
    cudaGetSymbolAddress((void**)&x1,    g_x1);
    cudaGetSymbolAddress((void**)&wqT,   g_wqT);
    cudaGetSymbolAddress((void**)&wkvT,  g_wkvT);
    cudaGetSymbolAddress((void**)&woT,   g_woT);
    cudaGetSymbolAddress((void**)&w1T,   g_w1T);
    cudaGetSymbolAddress((void**)&w2T,   g_w2T);

    cudaFuncSetAttribute(attn_kernel, cudaFuncAttributeMaxDynamicSharedMemorySize, ATT_SMEM);
    cudaFuncSetAttribute(qkv_gemm,    cudaFuncAttributeMaxDynamicSharedMemorySize, GEMM_SMEM);
    cudaFuncSetAttribute(mma_gemm<2>, cudaFuncAttributeMaxDynamicSharedMemorySize, GEMM_SMEM);
    cudaFuncSetAttribute(mma_gemm<3>, cudaFuncAttributeMaxDynamicSharedMemorySize, GEMM_SMEM);

    static cudaStream_t s2 = nullptr;
    static cudaEvent_t eBegin = nullptr, eQKVw = nullptr, eW = nullptr;
    if (s2 == nullptr) {
        cudaStreamCreateWithFlags(&s2, cudaStreamNonBlocking);
        cudaEventCreateWithFlags(&eBegin, cudaEventDisableTiming);
        cudaEventCreateWithFlags(&eQKVw,  cudaEventDisableTiming);
        cudaEventCreateWithFlags(&eW,     cudaEventDisableTiming);
    }

    // ---- fork: weight transposes on s2 ----
    cudaEventRecord(eBegin, 0);
    cudaStreamWaitEvent(s2, eBegin, 0);
    transpose_h_kernel<<<dim3(DIM / 32, DIM / 32), 256, 0, s2>>>(Wq,  wqT,  DIM,  DIM);
    transpose_h_kernel<<<dim3(2 * DIM / 32, DIM / 32), 256, 0, s2>>>(Wkv, wkvT, DIM, 2 * DIM);
    cudaEventRecord(eQKVw, s2);
    transpose_h_kernel<<<dim3(DIM / 32, DIM / 32), 256, 0, s2>>>(Wo,  woT,  DIM,  DIM);
    transpose_h_kernel<<<dim3(DFF_ / 32, DIM / 32), 256, 0, s2>>>(W1,  w1T,  DIM,  DFF_);
    transpose_h_kernel<<<dim3(DIM / 32, DFF_ / 32), 256, 0, s2>>>(W2,  w2T,  DFF_, DIM);
    cudaEventRecord(eW, s2);

    // main: activation convert
    convert_h_kernel<<<TOTK * DIM / (256 * 8), 256>>>(x, ctx, inh);

    // 1+2) merged QKV projection (Q gets alpha = log2e/8)
    cudaStreamWaitEvent(0, eQKVw, 0);
    qkv_gemm<<<640, 128, GEMM_SMEM>>>(inh, wqT, wkvT, bq, bkv, qh, kvh,
                                      0.18033688011112042f);

    // 3) attention -> attnh
    attn_kernel<<<dim3(SEQ_N / QROWS, HEADS), 512, ATT_SMEM>>>(qh, kvh, attnh);

    // ---- join: remaining weights ready ----
    cudaStreamWaitEvent(0, eW, 0);

    // 4) t = attn @ Wo + bo + x
    mma_gemm<3><<<dim3(DIM / 128, SEQ_N / 128), 128, GEMM_SMEM>>>(
        attnh, woT, bo, x, t, nullptr, DIM, DIM);

    // 5) x1 = LN1(t)
    ln_kernel<true><<<SEQ_N, 256>>>(t, ln1g, ln1b, x1, x1h);

    // 6) ffh = gelu(x1 @ W1 + bf1)
    mma_gemm<2><<<dim3(DFF_ / 128, SEQ_N / 128), 128, GEMM_SMEM>>>(
        x1h, w1T, bf1, nullptr, nullptr, ffh, DFF_, DIM);

    // 7) t = ff @ W2 + bf2 + x1
    mma_gemm<3><<<dim3(DIM / 128, SEQ_N / 128), 128, GEMM_SMEM>>>(
        ffh, w2T, bf2, x1, t, nullptr, DIM, DFF_);

    // 8) out = LN2(t)
    ln_kernel<false><<<SEQ_N, 256>>>(t, ln2g, ln2b, out, nullptr);
}